// round 15
// baseline (speedup 1.0000x reference)
#include <cuda_runtime.h>
#include <cuda_fp16.h>
#include <cstdint>
#include <math.h>

// Problem constants
#define Bdim 4
#define Ldim 8192
#define Ddim 512
#define Mdim (Bdim * Ldim)   // 32768
#define Ntot (2 * Ddim)      // 1024
#define Kdim 512

// GEMM tiling (mma.sync fp16 m16n8k16, cp.async 3-stage)
#define BM 256
#define BN 128
#define BK 64                            // k-halves per tile (128B rows)
#define NKT (Kdim / BK)                  // 8
#define KU (Kdim / 2)                    // 256 u32 per row of x_h / W_h
#define A_U32 (BM * 32)                  // 8192 u32 (32 u32/row)
#define B_U32 (BN * 32)                  // 4096 u32
#define STAGE_U32 (A_U32 + B_U32)        // 12288
#define NSTAGES 3
#define SMEM_BYTES (NSTAGES * STAGE_U32 * 4)   // 147456

// Scan config
#define CHUNK 64
#define NCHUNK (Ldim / CHUNK)        // 128
#define NBLK (Bdim * NCHUNK)         // 512 scan CTAs

// ---------------- scratch ----------------
__device__ float g_gate[(size_t)Mdim * Ddim];
__device__ float c_cand[(size_t)Mdim * Ddim];
__device__ uint32_t x_h[(size_t)Mdim * KU];     // x in half2-packed
__device__ uint32_t W_h[(size_t)Ntot * KU];     // [Wg;Wc] in half2-packed
__device__ float2 aggAB[(size_t)NBLK * Ddim];   // per-chunk (A,B) aggregates
__device__ volatile int scan_flag[NBLK];        // lookback flags

// ---------------- helpers ----------------
__device__ __forceinline__ uint32_t smem_u32(const void* p) {
    uint32_t a;
    asm("{ .reg .u64 t; cvta.to.shared.u64 t, %1; cvt.u32.u64 %0, t; }" : "=r"(a) : "l"(p));
    return a;
}
__device__ __forceinline__ uint32_t pack_h2(float lo, float hi) {
    uint32_t r;
    asm("{ .reg .b16 a, b;\n\t"
        "cvt.rn.f16.f32 a, %1;\n\t"
        "cvt.rn.f16.f32 b, %2;\n\t"
        "mov.b32 %0, {a, b}; }"
        : "=r"(r) : "f"(lo), "f"(hi));
    return r;
}
__device__ __forceinline__ void cp16(uint32_t dst, const void* src) {
    asm volatile("cp.async.cg.shared.global [%0], [%1], 16;" :: "r"(dst), "l"(src));
}
__device__ __forceinline__ void cp_commit() { asm volatile("cp.async.commit_group;" ::: "memory"); }
template <int N>
__device__ __forceinline__ void cp_wait() { asm volatile("cp.async.wait_group %0;" :: "n"(N) : "memory"); }

__device__ __forceinline__ void mma_f16(float c[4], const uint32_t a[4], const uint32_t b[2]) {
    asm volatile(
        "mma.sync.aligned.m16n8k16.row.col.f32.f16.f16.f32 "
        "{%0,%1,%2,%3}, {%4,%5,%6,%7}, {%8,%9}, {%0,%1,%2,%3};\n"
        : "+f"(c[0]), "+f"(c[1]), "+f"(c[2]), "+f"(c[3])
        : "r"(a[0]), "r"(a[1]), "r"(a[2]), "r"(a[3]), "r"(b[0]), "r"(b[1]));
}

// XOR-swizzled smem u32 index (row stride 32 u32 / 128B)
__device__ __forceinline__ int swz(int row, int col) {
    return (row << 5) + ((((col >> 2) ^ (row & 7)) << 2) | (col & 3));
}

// ---------------- convert x / W to fp16 (+ flag reset) ----------------
__global__ void convert_x_kernel(const float* __restrict__ x)
{
    size_t i = (size_t)blockIdx.x * 256 + threadIdx.x;   // float4 slots
    float4 v = reinterpret_cast<const float4*>(x)[i];
    uint2 o;
    o.x = pack_h2(v.x, v.y);
    o.y = pack_h2(v.z, v.w);
    reinterpret_cast<uint2*>(x_h)[i] = o;
}
__global__ void convert_w_kernel(const float* __restrict__ Wg, const float* __restrict__ Wc)
{
    int i = blockIdx.x * 256 + threadIdx.x;              // float4 slots: 262144
    if (i < NBLK) scan_flag[i] = 0;                      // reset lookback flags each replay
    const int half_n = (Ntot / 2) * Kdim / 4;            // 65536
    const float4* src = (i < half_n) ? (const float4*)Wg : (const float4*)Wc;
    int j = (i < half_n) ? i : i - half_n;
    float4 v = src[j];
    uint2 o;
    o.x = pack_h2(v.x, v.y);
    o.y = pack_h2(v.z, v.w);
    reinterpret_cast<uint2*>(W_h)[i] = o;
}

// ---------------- fused GEMM + activation ----------------
__global__ __launch_bounds__(512, 1) void gemm_act_kernel(
    const float* __restrict__ bg, const float* __restrict__ bc)
{
    extern __shared__ uint32_t smu[];
    const uint32_t smem_base = smem_u32(smu);

    const int m0 = blockIdx.y * BM;
    const int n0 = blockIdx.x * BN;
    const bool isGate = (n0 < Ddim);
    const uint32_t* Wp = W_h + (size_t)n0 * KU;

    const int tid  = threadIdx.x;
    const int warp = tid >> 5;
    const int lane = tid & 31;
    const int wm = warp >> 2;                // 0..3 -> 64 rows each
    const int wn = warp & 3;                 // 0..3 -> 32 cols each
    const int g  = lane >> 2;
    const int tg = lane & 3;

    auto load_stage = [&](int kt) {
        const uint32_t base  = smem_base + (kt % NSTAGES) * (STAGE_U32 * 4);
        const uint32_t bbase = base + A_U32 * 4;
        const int k0 = kt * 32;              // u32 offset in row
        #pragma unroll
        for (int r = 0; r < 4; ++r) {
            int i = tid + (r << 9);
            int row = i >> 3, j = i & 7;
            cp16(base + 4 * ((row << 5) + ((j ^ (row & 7)) << 2)),
                 x_h + (size_t)(m0 + row) * KU + k0 + j * 4);
        }
        #pragma unroll
        for (int r = 0; r < 2; ++r) {
            int i = tid + (r << 9);
            int row = i >> 3, j = i & 7;
            cp16(bbase + 4 * ((row << 5) + ((j ^ (row & 7)) << 2)),
                 Wp + (size_t)row * KU + k0 + j * 4);
        }
        cp_commit();
    };

    float acc[4][4][4];
    #pragma unroll
    for (int mt = 0; mt < 4; ++mt)
        #pragma unroll
        for (int nt = 0; nt < 4; ++nt)
            #pragma unroll
            for (int i = 0; i < 4; ++i) acc[mt][nt][i] = 0.0f;

    load_stage(0);
    load_stage(1);

    for (int s = 0; s < NKT; ++s) {
        if (s < NKT - 2) cp_wait<1>(); else cp_wait<0>();
        __syncthreads();                         // single barrier per k-tile

        if (s + 2 < NKT) load_stage(s + 2);      // slot (s+2)%3 last read in compute(s-1)

        const uint32_t* As = smu + (s % NSTAGES) * STAGE_U32;
        const uint32_t* Bs = As + A_U32;
        #pragma unroll
        for (int ks = 0; ks < 4; ++ks) {
            const int k = ks * 8;
            uint32_t af[4][4], bf[4][2];
            #pragma unroll
            for (int mt = 0; mt < 4; ++mt) {
                int r = wm * 64 + mt * 16;
                af[mt][0] = As[swz(r + g,     k + tg)];
                af[mt][1] = As[swz(r + g + 8, k + tg)];
                af[mt][2] = As[swz(r + g,     k + tg + 4)];
                af[mt][3] = As[swz(r + g + 8, k + tg + 4)];
            }
            #pragma unroll
            for (int nt = 0; nt < 4; ++nt) {
                int n = wn * 32 + nt * 8 + g;
                bf[nt][0] = Bs[swz(n, k + tg)];
                bf[nt][1] = Bs[swz(n, k + tg + 4)];
            }
            #pragma unroll
            for (int mt = 0; mt < 4; ++mt)
                #pragma unroll
                for (int nt = 0; nt < 4; ++nt)
                    mma_f16(acc[mt][nt], af[mt], bf[nt]);
        }
    }

    // epilogue: bias + activation
    float* dst = isGate ? g_gate : c_cand;
    const float* bias = isGate ? bg : bc;
    const int cb = n0 & (Ddim - 1);
    #pragma unroll
    for (int mt = 0; mt < 4; ++mt) {
        #pragma unroll
        for (int nt = 0; nt < 4; ++nt) {
            int row0 = m0 + wm * 64 + mt * 16 + g;
            int col  = cb + wn * 32 + nt * 8 + 2 * tg;
            float b0v = bias[col], b1v = bias[col + 1];
            float2 o0, o1;
            if (isGate) {
                o0.x = 1.0f / (1.0f + expf(-(acc[mt][nt][0] + b0v)));
                o0.y = 1.0f / (1.0f + expf(-(acc[mt][nt][1] + b1v)));
                o1.x = 1.0f / (1.0f + expf(-(acc[mt][nt][2] + b0v)));
                o1.y = 1.0f / (1.0f + expf(-(acc[mt][nt][3] + b1v)));
            } else {
                o0.x = tanhf(acc[mt][nt][0] + b0v);
                o0.y = tanhf(acc[mt][nt][1] + b1v);
                o1.x = tanhf(acc[mt][nt][2] + b0v);
                o1.y = tanhf(acc[mt][nt][3] + b1v);
            }
            *reinterpret_cast<float2*>(&dst[(size_t)row0 * Ddim + col]) = o0;
            *reinterpret_cast<float2*>(&dst[(size_t)(row0 + 8) * Ddim + col]) = o1;
        }
    }
}

// ---------------- fused single-pass scan (decoupled lookback) ----------------
// One CTA per (batch, chunk). Local reduce -> publish (A,B) -> lookback
// (early-exits when composed A underflows to 0, which is exact) -> final pass.
__global__ __launch_bounds__(Ddim) void scan_fused(float* __restrict__ out)
{
    const int bid = blockIdx.x;
    const int b = bid >> 7;                 // / NCHUNK
    const int j = bid & (NCHUNK - 1);
    const int d = threadIdx.x;
    const size_t base = ((size_t)b * Ldim + (size_t)j * CHUNK) * Ddim + d;
    const float* gp = g_gate + base;
    const float* cp = c_cand + base;

    // local chunk reduce
    float A = 1.0f, Bv = 0.0f;
    #pragma unroll 4
    for (int t = 0; t < CHUNK; ++t) {
        float gv = gp[(size_t)t * Ddim];
        float cv = cp[(size_t)t * Ddim];
        float a = 1.0f - gv;
        Bv = fmaf(a, Bv, gv * cv);
        A  = a * A;
    }

    // publish aggregate
    aggAB[(size_t)bid * Ddim + d] = make_float2(A, Bv);
    __threadfence();
    __syncthreads();
    if (d == 0) atomicExch((int*)&scan_flag[bid], 1);

    // lookback: h_start = B of composition of chunks [0..j-1]
    float h = 0.0f;
    if (j > 0) {
        float rA = 1.0f, rB = 0.0f;         // composed map over [k+1..j-1]
        for (int k = j - 1; k >= 0; --k) {
            if (d == 0) { while (scan_flag[b * NCHUNK + k] == 0) {} }
            __syncthreads();
            float2 agg = __ldcg(&aggAB[(size_t)(b * NCHUNK + k) * Ddim + d]);
            rB = fmaf(rA, agg.y, rB);       // include chunk k (applied first)
            rA = rA * agg.x;
            if (__syncthreads_and(rA == 0.0f)) break;   // earlier chunks contribute 0
        }
        h = rB;
    }

    // final pass: emit h (re-reads are L2-hot)
    float* op = out + base;
    #pragma unroll 4
    for (int t = 0; t < CHUNK; ++t) {
        float gv = gp[(size_t)t * Ddim];
        float cv = cp[(size_t)t * Ddim];
        h = fmaf(gv, cv - h, h);
        op[(size_t)t * Ddim] = h;
    }
}

// ---------------- launch ----------------
extern "C" void kernel_launch(void* const* d_in, const int* in_sizes, int n_in,
                              void* d_out, int out_size)
{
    const float* x  = (const float*)d_in[0];
    const float* Wg = (const float*)d_in[1];
    const float* bg = (const float*)d_in[2];
    const float* Wc = (const float*)d_in[3];
    const float* bc = (const float*)d_in[4];
    float* out = (float*)d_out;

    cudaFuncSetAttribute(gemm_act_kernel,
                         cudaFuncAttributeMaxDynamicSharedMemorySize, SMEM_BYTES);

    convert_x_kernel<<<(Mdim * Kdim / 4) / 256, 256>>>(x);      // 16384 blocks
    convert_w_kernel<<<(Ntot * Kdim / 4) / 256, 256>>>(Wg, Wc); // 1024 blocks (also resets flags)
    dim3 gemm_grid(Ntot / BN, Mdim / BM);           // (8, 128) = 1024 CTAs
    gemm_act_kernel<<<gemm_grid, 512, SMEM_BYTES>>>(bg, bc);
    scan_fused<<<NBLK, Ddim>>>(out);                // 512 CTAs, all resident
}

// round 16
// speedup vs baseline: 1.1444x; 1.1444x over previous
#include <cuda_runtime.h>
#include <cuda_fp16.h>
#include <cstdint>
#include <math.h>

// Problem constants
#define Bdim 4
#define Ldim 8192
#define Ddim 512
#define Mdim (Bdim * Ldim)   // 32768
#define Ntot (2 * Ddim)      // 1024
#define Kdim 512

// GEMM tiling (mma.sync fp16 m16n8k16, cp.async 3-stage)
#define BM 256
#define BN 128
#define BK 64                            // k-halves per tile (128B rows)
#define NKT (Kdim / BK)                  // 8
#define KU (Kdim / 2)                    // 256 u32 per row of x_h / W_h
#define A_U32 (BM * 32)                  // 8192 u32 (32 u32/row)
#define B_U32 (BN * 32)                  // 4096 u32
#define STAGE_U32 (A_U32 + B_U32)        // 12288
#define NSTAGES 3
#define SMEM_BYTES (NSTAGES * STAGE_U32 * 4)   // 147456

// Scan config
#define CHUNK 32
#define NCHUNK (Ldim / CHUNK)        // 256
#define NCHAN (Bdim * Ddim)          // 2048
#define DU (Ddim / 2)                // 256 u32 per row of g_h/c_h

// ---------------- scratch ----------------
__device__ uint32_t g_h[(size_t)Mdim * DU];     // sigmoid(.), half2-packed [B,L,D/2]
__device__ uint32_t c_h[(size_t)Mdim * DU];     // tanh(.),    half2-packed
__device__ uint32_t x_h[(size_t)Mdim * KU];     // x in half2-packed
__device__ uint32_t W_h[(size_t)Ntot * KU];     // [Wg;Wc] in half2-packed
__device__ float2 chunkAB[(size_t)NCHUNK * NCHAN];  // [chunk][channel]
__device__ float  chunkH[(size_t)NCHUNK * NCHAN];   // [chunk][channel]

// ---------------- helpers ----------------
__device__ __forceinline__ uint32_t smem_u32(const void* p) {
    uint32_t a;
    asm("{ .reg .u64 t; cvta.to.shared.u64 t, %1; cvt.u32.u64 %0, t; }" : "=r"(a) : "l"(p));
    return a;
}
__device__ __forceinline__ uint32_t pack_h2(float lo, float hi) {
    uint32_t r;
    asm("{ .reg .b16 a, b;\n\t"
        "cvt.rn.f16.f32 a, %1;\n\t"
        "cvt.rn.f16.f32 b, %2;\n\t"
        "mov.b32 %0, {a, b}; }"
        : "=r"(r) : "f"(lo), "f"(hi));
    return r;
}
__device__ __forceinline__ float2 unpack_h2(uint32_t v) {
    float lo, hi;
    asm("{ .reg .b16 a, b;\n\t"
        "mov.b32 {a, b}, %2;\n\t"
        "cvt.f32.f16 %0, a;\n\t"
        "cvt.f32.f16 %1, b; }"
        : "=f"(lo), "=f"(hi) : "r"(v));
    return make_float2(lo, hi);
}
__device__ __forceinline__ void cp16(uint32_t dst, const void* src) {
    asm volatile("cp.async.cg.shared.global [%0], [%1], 16;" :: "r"(dst), "l"(src));
}
__device__ __forceinline__ void cp_commit() { asm volatile("cp.async.commit_group;" ::: "memory"); }
template <int N>
__device__ __forceinline__ void cp_wait() { asm volatile("cp.async.wait_group %0;" :: "n"(N) : "memory"); }

__device__ __forceinline__ void mma_f16(float c[4], const uint32_t a[4], const uint32_t b[2]) {
    asm volatile(
        "mma.sync.aligned.m16n8k16.row.col.f32.f16.f16.f32 "
        "{%0,%1,%2,%3}, {%4,%5,%6,%7}, {%8,%9}, {%0,%1,%2,%3};\n"
        : "+f"(c[0]), "+f"(c[1]), "+f"(c[2]), "+f"(c[3])
        : "r"(a[0]), "r"(a[1]), "r"(a[2]), "r"(a[3]), "r"(b[0]), "r"(b[1]));
}

// XOR-swizzled smem u32 index (row stride 32 u32 / 128B)
__device__ __forceinline__ int swz(int row, int col) {
    return (row << 5) + ((((col >> 2) ^ (row & 7)) << 2) | (col & 3));
}

// ---------------- convert x / W to fp16 ----------------
__global__ void convert_x_kernel(const float* __restrict__ x)
{
    size_t i = (size_t)blockIdx.x * 256 + threadIdx.x;   // float4 slots
    float4 v = reinterpret_cast<const float4*>(x)[i];
    uint2 o;
    o.x = pack_h2(v.x, v.y);
    o.y = pack_h2(v.z, v.w);
    reinterpret_cast<uint2*>(x_h)[i] = o;
}
__global__ void convert_w_kernel(const float* __restrict__ Wg, const float* __restrict__ Wc)
{
    int i = blockIdx.x * 256 + threadIdx.x;              // float4 slots: 262144
    const int half_n = (Ntot / 2) * Kdim / 4;            // 65536
    const float4* src = (i < half_n) ? (const float4*)Wg : (const float4*)Wc;
    int j = (i < half_n) ? i : i - half_n;
    float4 v = src[j];
    uint2 o;
    o.x = pack_h2(v.x, v.y);
    o.y = pack_h2(v.z, v.w);
    reinterpret_cast<uint2*>(W_h)[i] = o;
}

// ---------------- fused GEMM + activation (R13 structure) ----------------
__global__ __launch_bounds__(512, 1) void gemm_act_kernel(
    const float* __restrict__ bg, const float* __restrict__ bc)
{
    extern __shared__ uint32_t smu[];
    const uint32_t smem_base = smem_u32(smu);

    const int m0 = blockIdx.y * BM;
    const int n0 = blockIdx.x * BN;
    const bool isGate = (n0 < Ddim);
    const uint32_t* Wp = W_h + (size_t)n0 * KU;

    const int tid  = threadIdx.x;
    const int warp = tid >> 5;
    const int lane = tid & 31;
    const int wm = warp >> 2;                // 0..3 -> 64 rows each
    const int wn = warp & 3;                 // 0..3 -> 32 cols each
    const int g  = lane >> 2;
    const int tg = lane & 3;

    auto load_stage = [&](int kt) {
        const uint32_t base  = smem_base + (kt % NSTAGES) * (STAGE_U32 * 4);
        const uint32_t bbase = base + A_U32 * 4;
        const int k0 = kt * 32;              // u32 offset in row
        #pragma unroll
        for (int r = 0; r < 4; ++r) {
            int i = tid + (r << 9);
            int row = i >> 3, j = i & 7;
            cp16(base + 4 * ((row << 5) + ((j ^ (row & 7)) << 2)),
                 x_h + (size_t)(m0 + row) * KU + k0 + j * 4);
        }
        #pragma unroll
        for (int r = 0; r < 2; ++r) {
            int i = tid + (r << 9);
            int row = i >> 3, j = i & 7;
            cp16(bbase + 4 * ((row << 5) + ((j ^ (row & 7)) << 2)),
                 Wp + (size_t)row * KU + k0 + j * 4);
        }
        cp_commit();
    };

    float acc[4][4][4];
    #pragma unroll
    for (int mt = 0; mt < 4; ++mt)
        #pragma unroll
        for (int nt = 0; nt < 4; ++nt)
            #pragma unroll
            for (int i = 0; i < 4; ++i) acc[mt][nt][i] = 0.0f;

    load_stage(0);
    load_stage(1);

    for (int s = 0; s < NKT; ++s) {
        if (s < NKT - 2) cp_wait<1>(); else cp_wait<0>();
        __syncthreads();

        const uint32_t* As = smu + (s % NSTAGES) * STAGE_U32;
        const uint32_t* Bs = As + A_U32;
        #pragma unroll
        for (int ks = 0; ks < 4; ++ks) {
            const int k = ks * 8;
            uint32_t af[4][4], bf[4][2];
            #pragma unroll
            for (int mt = 0; mt < 4; ++mt) {
                int r = wm * 64 + mt * 16;
                af[mt][0] = As[swz(r + g,     k + tg)];
                af[mt][1] = As[swz(r + g + 8, k + tg)];
                af[mt][2] = As[swz(r + g,     k + tg + 4)];
                af[mt][3] = As[swz(r + g + 8, k + tg + 4)];
            }
            #pragma unroll
            for (int nt = 0; nt < 4; ++nt) {
                int n = wn * 32 + nt * 8 + g;
                bf[nt][0] = Bs[swz(n, k + tg)];
                bf[nt][1] = Bs[swz(n, k + tg + 4)];
            }
            #pragma unroll
            for (int mt = 0; mt < 4; ++mt)
                #pragma unroll
                for (int nt = 0; nt < 4; ++nt)
                    mma_f16(acc[mt][nt], af[mt], bf[nt]);
        }
        __syncthreads();

        if (s + 2 < NKT) load_stage(s + 2);
    }

    // epilogue: bias + activation, pack to half2
    uint32_t* dst = isGate ? g_h : c_h;
    const float* bias = isGate ? bg : bc;
    const int cb = n0 & (Ddim - 1);
    #pragma unroll
    for (int mt = 0; mt < 4; ++mt) {
        #pragma unroll
        for (int nt = 0; nt < 4; ++nt) {
            int row0 = m0 + wm * 64 + mt * 16 + g;
            int col  = cb + wn * 32 + nt * 8 + 2 * tg;   // even
            float b0v = bias[col], b1v = bias[col + 1];
            float v00, v01, v10, v11;
            if (isGate) {
                v00 = 1.0f / (1.0f + expf(-(acc[mt][nt][0] + b0v)));
                v01 = 1.0f / (1.0f + expf(-(acc[mt][nt][1] + b1v)));
                v10 = 1.0f / (1.0f + expf(-(acc[mt][nt][2] + b0v)));
                v11 = 1.0f / (1.0f + expf(-(acc[mt][nt][3] + b1v)));
            } else {
                v00 = tanhf(acc[mt][nt][0] + b0v);
                v01 = tanhf(acc[mt][nt][1] + b1v);
                v10 = tanhf(acc[mt][nt][2] + b0v);
                v11 = tanhf(acc[mt][nt][3] + b1v);
            }
            dst[((size_t)row0 * Ddim + col) >> 1]       = pack_h2(v00, v01);
            dst[((size_t)(row0 + 8) * Ddim + col) >> 1] = pack_h2(v10, v11);
        }
    }
}

// ---------------- scan phase 1: per-chunk (A,B), 2 channels/thread --------
__global__ __launch_bounds__(256) void scan_phase1(void)
{
    const int bid = blockIdx.x;
    const int b = bid >> 8;                  // / NCHUNK
    const int j = bid & (NCHUNK - 1);
    const int tid = threadIdx.x;
    const size_t base_u = ((size_t)b * Ldim + (size_t)j * CHUNK) * DU + tid;

    float A0 = 1.0f, B0 = 0.0f, A1 = 1.0f, B1 = 0.0f;
    #pragma unroll 4
    for (int t = 0; t < CHUNK; ++t) {
        float2 gv = unpack_h2(g_h[base_u + (size_t)t * DU]);
        float2 cv = unpack_h2(c_h[base_u + (size_t)t * DU]);
        float a0 = 1.0f - gv.x, a1 = 1.0f - gv.y;
        B0 = fmaf(a0, B0, gv.x * cv.x);  A0 *= a0;
        B1 = fmaf(a1, B1, gv.y * cv.y);  A1 *= a1;
    }
    // [chunk][channel] layout, float4 write (channels 2*tid, 2*tid+1)
    *reinterpret_cast<float4*>(&chunkAB[(size_t)j * NCHAN + b * Ddim + 2 * tid]) =
        make_float4(A0, B0, A1, B1);
}

// ---------------- scan phase 2: warp per channel, 256 chunks (8/lane) -----
__global__ __launch_bounds__(256) void scan_phase2(void)
{
    const int warp = threadIdx.x >> 5;
    const int lane = threadIdx.x & 31;
    const int ch = blockIdx.x * 8 + warp;    // 0..2047 (= b*Ddim + d)

    float2 v[8];
    #pragma unroll
    for (int i = 0; i < 8; ++i)
        v[i] = chunkAB[(size_t)(8 * lane + i) * NCHAN + ch];

    // compose the 8 (v[0] applied first)
    float2 p = v[0];
    #pragma unroll
    for (int i = 1; i < 8; ++i) {
        p.y = fmaf(v[i].x, p.y, v[i].y);
        p.x = v[i].x * p.x;
    }
    #pragma unroll
    for (int off = 1; off < 32; off <<= 1) {
        float ap = __shfl_up_sync(0xffffffffu, p.x, off);
        float bp = __shfl_up_sync(0xffffffffu, p.y, off);
        if (lane >= off) {
            p.y = fmaf(p.x, bp, p.y);
            p.x = p.x * ap;
        }
    }
    float h = __shfl_up_sync(0xffffffffu, p.y, 1);
    if (lane == 0) h = 0.0f;

    #pragma unroll
    for (int i = 0; i < 8; ++i) {
        chunkH[(size_t)(8 * lane + i) * NCHAN + ch] = h;
        h = fmaf(v[i].x, h, v[i].y);
    }
}

// ---------------- scan phase 3: apply prefix, emit h (fp32 out) -----------
__global__ __launch_bounds__(256) void scan_phase3(float* __restrict__ out)
{
    const int bid = blockIdx.x;
    const int b = bid >> 8;
    const int j = bid & (NCHUNK - 1);
    const int tid = threadIdx.x;
    const size_t base_u = ((size_t)b * Ldim + (size_t)j * CHUNK) * DU + tid;
    float* op = out + ((size_t)b * Ldim + (size_t)j * CHUNK) * Ddim + 2 * tid;

    float2 h = *reinterpret_cast<float2*>(&chunkH[(size_t)j * NCHAN + b * Ddim + 2 * tid]);
    #pragma unroll 4
    for (int t = 0; t < CHUNK; ++t) {
        float2 gv = unpack_h2(g_h[base_u + (size_t)t * DU]);
        float2 cv = unpack_h2(c_h[base_u + (size_t)t * DU]);
        h.x = fmaf(gv.x, cv.x - h.x, h.x);
        h.y = fmaf(gv.y, cv.y - h.y, h.y);
        *reinterpret_cast<float2*>(op + (size_t)t * Ddim) = h;
    }
}

// ---------------- launch ----------------
extern "C" void kernel_launch(void* const* d_in, const int* in_sizes, int n_in,
                              void* d_out, int out_size)
{
    const float* x  = (const float*)d_in[0];
    const float* Wg = (const float*)d_in[1];
    const float* bg = (const float*)d_in[2];
    const float* Wc = (const float*)d_in[3];
    const float* bc = (const float*)d_in[4];
    float* out = (float*)d_out;

    cudaFuncSetAttribute(gemm_act_kernel,
                         cudaFuncAttributeMaxDynamicSharedMemorySize, SMEM_BYTES);

    convert_x_kernel<<<(Mdim * Kdim / 4) / 256, 256>>>(x);      // 16384 blocks
    convert_w_kernel<<<(Ntot * Kdim / 4) / 256, 256>>>(Wg, Wc); // 1024 blocks
    dim3 gemm_grid(Ntot / BN, Mdim / BM);           // (8, 128) = 1024 CTAs
    gemm_act_kernel<<<gemm_grid, 512, SMEM_BYTES>>>(bg, bc);
    scan_phase1<<<Bdim * NCHUNK, 256>>>();          // 1024 blocks
    scan_phase2<<<NCHAN / 8, 256>>>();
    scan_phase3<<<Bdim * NCHUNK, 256>>>(out);       // 1024 blocks
}

// round 17
// speedup vs baseline: 1.5789x; 1.3797x over previous
#include <cuda_runtime.h>
#include <cuda_fp16.h>
#include <cstdint>
#include <math.h>

// Problem constants
#define Bdim 4
#define Ldim 8192
#define Ddim 512
#define Mdim (Bdim * Ldim)   // 32768
#define Ntot (2 * Ddim)      // 1024
#define Kdim 512

// GEMM tiling (mma.sync fp16 m16n8k16, cp.async 3-stage, ldmatrix fragments)
#define BM 256
#define BN 128
#define BK 64                            // k-halves per tile (128B rows)
#define NKT (Kdim / BK)                  // 8
#define KU (Kdim / 2)                    // 256 u32 per row of x_h / W_h
#define A_U32 (BM * 32)                  // 8192 u32 (32 u32/row)
#define B_U32 (BN * 32)                  // 4096 u32
#define STAGE_U32 (A_U32 + B_U32)        // 12288
#define NSTAGES 3
#define SMEM_BYTES (NSTAGES * STAGE_U32 * 4)   // 147456

// Scan config
#define CHUNK 32
#define NCHUNK (Ldim / CHUNK)        // 256
#define NCHAN (Bdim * Ddim)          // 2048
#define DU (Ddim / 2)                // 256 u32 per row of g_h/c_h

// ---------------- scratch ----------------
__device__ uint32_t g_h[(size_t)Mdim * DU];     // sigmoid(.), half2-packed [B,L,D/2]
__device__ uint32_t c_h[(size_t)Mdim * DU];     // tanh(.),    half2-packed
__device__ uint32_t x_h[(size_t)Mdim * KU];     // x in half2-packed
__device__ uint32_t W_h[(size_t)Ntot * KU];     // [Wg;Wc] in half2-packed
__device__ float2 chunkAB[(size_t)NCHUNK * NCHAN];  // [chunk][channel]
__device__ float  chunkH[(size_t)NCHUNK * NCHAN];   // [chunk][channel]

// ---------------- helpers ----------------
__device__ __forceinline__ uint32_t smem_u32(const void* p) {
    uint32_t a;
    asm("{ .reg .u64 t; cvta.to.shared.u64 t, %1; cvt.u32.u64 %0, t; }" : "=r"(a) : "l"(p));
    return a;
}
__device__ __forceinline__ uint32_t pack_h2(float lo, float hi) {
    uint32_t r;
    asm("{ .reg .b16 a, b;\n\t"
        "cvt.rn.f16.f32 a, %1;\n\t"
        "cvt.rn.f16.f32 b, %2;\n\t"
        "mov.b32 %0, {a, b}; }"
        : "=r"(r) : "f"(lo), "f"(hi));
    return r;
}
__device__ __forceinline__ float2 unpack_h2(uint32_t v) {
    float lo, hi;
    asm("{ .reg .b16 a, b;\n\t"
        "mov.b32 {a, b}, %2;\n\t"
        "cvt.f32.f16 %0, a;\n\t"
        "cvt.f32.f16 %1, b; }"
        : "=f"(lo), "=f"(hi) : "r"(v));
    return make_float2(lo, hi);
}
__device__ __forceinline__ void cp16(uint32_t dst, const void* src) {
    asm volatile("cp.async.cg.shared.global [%0], [%1], 16;" :: "r"(dst), "l"(src));
}
__device__ __forceinline__ void cp_commit() { asm volatile("cp.async.commit_group;" ::: "memory"); }
template <int N>
__device__ __forceinline__ void cp_wait() { asm volatile("cp.async.wait_group %0;" :: "n"(N) : "memory"); }

__device__ __forceinline__ void mma_f16(float c[4], const uint32_t a[4], const uint32_t b[2]) {
    asm volatile(
        "mma.sync.aligned.m16n8k16.row.col.f32.f16.f16.f32 "
        "{%0,%1,%2,%3}, {%4,%5,%6,%7}, {%8,%9}, {%0,%1,%2,%3};\n"
        : "+f"(c[0]), "+f"(c[1]), "+f"(c[2]), "+f"(c[3])
        : "r"(a[0]), "r"(a[1]), "r"(a[2]), "r"(a[3]), "r"(b[0]), "r"(b[1]));
}
__device__ __forceinline__ void ldm_x4(uint32_t d[4], uint32_t addr) {
    asm volatile("ldmatrix.sync.aligned.m8n8.x4.shared.b16 {%0,%1,%2,%3}, [%4];"
                 : "=r"(d[0]), "=r"(d[1]), "=r"(d[2]), "=r"(d[3]) : "r"(addr));
}

// ---------------- convert x / W to fp16 ----------------
__global__ void convert_x_kernel(const float* __restrict__ x)
{
    size_t i = (size_t)blockIdx.x * 256 + threadIdx.x;   // float4 slots
    float4 v = reinterpret_cast<const float4*>(x)[i];
    uint2 o;
    o.x = pack_h2(v.x, v.y);
    o.y = pack_h2(v.z, v.w);
    reinterpret_cast<uint2*>(x_h)[i] = o;
}
__global__ void convert_w_kernel(const float* __restrict__ Wg, const float* __restrict__ Wc)
{
    int i = blockIdx.x * 256 + threadIdx.x;              // float4 slots: 262144
    const int half_n = (Ntot / 2) * Kdim / 4;            // 65536
    const float4* src = (i < half_n) ? (const float4*)Wg : (const float4*)Wc;
    int j = (i < half_n) ? i : i - half_n;
    float4 v = src[j];
    uint2 o;
    o.x = pack_h2(v.x, v.y);
    o.y = pack_h2(v.z, v.w);
    reinterpret_cast<uint2*>(W_h)[i] = o;
}

// ---------------- fused GEMM + activation ----------------
__global__ __launch_bounds__(512, 1) void gemm_act_kernel(
    const float* __restrict__ bg, const float* __restrict__ bc)
{
    extern __shared__ uint32_t smu[];
    const uint32_t smem_base = smem_u32(smu);

    const int m0 = blockIdx.y * BM;
    const int n0 = blockIdx.x * BN;
    const bool isGate = (n0 < Ddim);
    const uint32_t* Wp = W_h + (size_t)n0 * KU;

    const int tid  = threadIdx.x;
    const int warp = tid >> 5;
    const int lane = tid & 31;
    const int wm = warp >> 2;                // 0..3 -> 64 rows each
    const int wn = warp & 3;                 // 0..3 -> 32 cols each
    const int g  = lane >> 2;
    const int tg = lane & 3;

    // ldmatrix per-lane address components
    const int arow = wm * 64 + (lane & 15);          // A row for this lane
    const int ahi  = lane >> 4;                      // 0: k-lo chunk, 1: k-hi
    const int asx  = arow & 7;                       // swizzle XOR (mt-invariant)
    const int brow = wn * 32 + ((lane >> 4) << 3) + (lane & 7);  // B row (c-invariant &7)
    const int bpar = (lane >> 3) & 1;                // b0 / b1 chunk parity
    const int bsx  = brow & 7;

    auto load_stage = [&](int kt) {
        const uint32_t base  = smem_base + (kt % NSTAGES) * (STAGE_U32 * 4);
        const uint32_t bbase = base + A_U32 * 4;
        const int k0 = kt * 32;              // u32 offset in row
        #pragma unroll
        for (int r = 0; r < 4; ++r) {
            int i = tid + (r << 9);
            int row = i >> 3, j = i & 7;
            cp16(base + 4 * ((row << 5) + ((j ^ (row & 7)) << 2)),
                 x_h + (size_t)(m0 + row) * KU + k0 + j * 4);
        }
        #pragma unroll
        for (int r = 0; r < 2; ++r) {
            int i = tid + (r << 9);
            int row = i >> 3, j = i & 7;
            cp16(bbase + 4 * ((row << 5) + ((j ^ (row & 7)) << 2)),
                 Wp + (size_t)row * KU + k0 + j * 4);
        }
        cp_commit();
    };

    float acc[4][4][4];
    #pragma unroll
    for (int mt = 0; mt < 4; ++mt)
        #pragma unroll
        for (int nt = 0; nt < 4; ++nt)
            #pragma unroll
            for (int i = 0; i < 4; ++i) acc[mt][nt][i] = 0.0f;

    load_stage(0);
    load_stage(1);

    for (int s = 0; s < NKT; ++s) {
        if (s < NKT - 2) cp_wait<1>(); else cp_wait<0>();
        __syncthreads();

        const uint32_t abase = smem_base + (s % NSTAGES) * (STAGE_U32 * 4);
        const uint32_t bbase = abase + A_U32 * 4;
        const uint32_t aladdr = abase + arow * 128;        // + mt*2048 + xor*16
        const uint32_t bladdr = bbase + brow * 128;        // + c*2048  + xor*16

        #pragma unroll
        for (int ks = 0; ks < 4; ++ks) {
            const uint32_t axor = (uint32_t)(((ks << 1) + ahi) ^ asx) << 4;
            const uint32_t bxor = (uint32_t)(((ks << 1) + bpar) ^ bsx) << 4;
            uint32_t af[4][4], bf[4][2];
            #pragma unroll
            for (int mt = 0; mt < 4; ++mt)
                ldm_x4(af[mt], aladdr + mt * 2048 + axor);
            #pragma unroll
            for (int c = 0; c < 2; ++c) {
                uint32_t bd[4];
                ldm_x4(bd, bladdr + c * 2048 + bxor);
                bf[2 * c][0] = bd[0];  bf[2 * c][1] = bd[1];
                bf[2 * c + 1][0] = bd[2];  bf[2 * c + 1][1] = bd[3];
            }
            #pragma unroll
            for (int mt = 0; mt < 4; ++mt)
                #pragma unroll
                for (int nt = 0; nt < 4; ++nt)
                    mma_f16(acc[mt][nt], af[mt], bf[nt]);
        }
        __syncthreads();

        if (s + 2 < NKT) load_stage(s + 2);
    }

    // epilogue: bias + activation, pack to half2
    uint32_t* dst = isGate ? g_h : c_h;
    const float* bias = isGate ? bg : bc;
    const int cb = n0 & (Ddim - 1);
    #pragma unroll
    for (int mt = 0; mt < 4; ++mt) {
        #pragma unroll
        for (int nt = 0; nt < 4; ++nt) {
            int row0 = m0 + wm * 64 + mt * 16 + g;
            int col  = cb + wn * 32 + nt * 8 + 2 * tg;   // even
            float b0v = bias[col], b1v = bias[col + 1];
            float v00, v01, v10, v11;
            if (isGate) {
                v00 = 1.0f / (1.0f + expf(-(acc[mt][nt][0] + b0v)));
                v01 = 1.0f / (1.0f + expf(-(acc[mt][nt][1] + b1v)));
                v10 = 1.0f / (1.0f + expf(-(acc[mt][nt][2] + b0v)));
                v11 = 1.0f / (1.0f + expf(-(acc[mt][nt][3] + b1v)));
            } else {
                v00 = tanhf(acc[mt][nt][0] + b0v);
                v01 = tanhf(acc[mt][nt][1] + b1v);
                v10 = tanhf(acc[mt][nt][2] + b0v);
                v11 = tanhf(acc[mt][nt][3] + b1v);
            }
            dst[((size_t)row0 * Ddim + col) >> 1]       = pack_h2(v00, v01);
            dst[((size_t)(row0 + 8) * Ddim + col) >> 1] = pack_h2(v10, v11);
        }
    }
}

// ---------------- scan phase 1: per-chunk (A,B), 2 channels/thread --------
__global__ __launch_bounds__(256) void scan_phase1(void)
{
    const int bid = blockIdx.x;
    const int b = bid >> 8;                  // / NCHUNK
    const int j = bid & (NCHUNK - 1);
    const int tid = threadIdx.x;
    const size_t base_u = ((size_t)b * Ldim + (size_t)j * CHUNK) * DU + tid;

    float A0 = 1.0f, B0 = 0.0f, A1 = 1.0f, B1 = 0.0f;
    #pragma unroll 4
    for (int t = 0; t < CHUNK; ++t) {
        float2 gv = unpack_h2(g_h[base_u + (size_t)t * DU]);
        float2 cv = unpack_h2(c_h[base_u + (size_t)t * DU]);
        float a0 = 1.0f - gv.x, a1 = 1.0f - gv.y;
        B0 = fmaf(a0, B0, gv.x * cv.x);  A0 *= a0;
        B1 = fmaf(a1, B1, gv.y * cv.y);  A1 *= a1;
    }
    *reinterpret_cast<float4*>(&chunkAB[(size_t)j * NCHAN + b * Ddim + 2 * tid]) =
        make_float4(A0, B0, A1, B1);
}

// ---------------- scan phase 2: warp per channel, 256 chunks (8/lane) -----
__global__ __launch_bounds__(256) void scan_phase2(void)
{
    const int warp = threadIdx.x >> 5;
    const int lane = threadIdx.x & 31;
    const int ch = blockIdx.x * 8 + warp;    // 0..2047 (= b*Ddim + d)

    float2 v[8];
    #pragma unroll
    for (int i = 0; i < 8; ++i)
        v[i] = chunkAB[(size_t)(8 * lane + i) * NCHAN + ch];

    float2 p = v[0];
    #pragma unroll
    for (int i = 1; i < 8; ++i) {
        p.y = fmaf(v[i].x, p.y, v[i].y);
        p.x = v[i].x * p.x;
    }
    #pragma unroll
    for (int off = 1; off < 32; off <<= 1) {
        float ap = __shfl_up_sync(0xffffffffu, p.x, off);
        float bp = __shfl_up_sync(0xffffffffu, p.y, off);
        if (lane >= off) {
            p.y = fmaf(p.x, bp, p.y);
            p.x = p.x * ap;
        }
    }
    float h = __shfl_up_sync(0xffffffffu, p.y, 1);
    if (lane == 0) h = 0.0f;

    #pragma unroll
    for (int i = 0; i < 8; ++i) {
        chunkH[(size_t)(8 * lane + i) * NCHAN + ch] = h;
        h = fmaf(v[i].x, h, v[i].y);
    }
}

// ---------------- scan phase 3: apply prefix, emit h (fp32 out) -----------
__global__ __launch_bounds__(256) void scan_phase3(float* __restrict__ out)
{
    const int bid = blockIdx.x;
    const int b = bid >> 8;
    const int j = bid & (NCHUNK - 1);
    const int tid = threadIdx.x;
    const size_t base_u = ((size_t)b * Ldim + (size_t)j * CHUNK) * DU + tid;
    float* op = out + ((size_t)b * Ldim + (size_t)j * CHUNK) * Ddim + 2 * tid;

    float2 h = *reinterpret_cast<float2*>(&chunkH[(size_t)j * NCHAN + b * Ddim + 2 * tid]);
    #pragma unroll 4
    for (int t = 0; t < CHUNK; ++t) {
        float2 gv = unpack_h2(g_h[base_u + (size_t)t * DU]);
        float2 cv = unpack_h2(c_h[base_u + (size_t)t * DU]);
        h.x = fmaf(gv.x, cv.x - h.x, h.x);
        h.y = fmaf(gv.y, cv.y - h.y, h.y);
        *reinterpret_cast<float2*>(op + (size_t)t * Ddim) = h;
    }
}

// ---------------- launch ----------------
extern "C" void kernel_launch(void* const* d_in, const int* in_sizes, int n_in,
                              void* d_out, int out_size)
{
    const float* x  = (const float*)d_in[0];
    const float* Wg = (const float*)d_in[1];
    const float* bg = (const float*)d_in[2];
    const float* Wc = (const float*)d_in[3];
    const float* bc = (const float*)d_in[4];
    float* out = (float*)d_out;

    cudaFuncSetAttribute(gemm_act_kernel,
                         cudaFuncAttributeMaxDynamicSharedMemorySize, SMEM_BYTES);

    convert_x_kernel<<<(Mdim * Kdim / 4) / 256, 256>>>(x);      // 16384 blocks
    convert_w_kernel<<<(Ntot * Kdim / 4) / 256, 256>>>(Wg, Wc); // 1024 blocks
    dim3 gemm_grid(Ntot / BN, Mdim / BM);           // (8, 128) = 1024 CTAs
    gemm_act_kernel<<<gemm_grid, 512, SMEM_BYTES>>>(bg, bc);
    scan_phase1<<<Bdim * NCHUNK, 256>>>();          // 1024 blocks
    scan_phase2<<<NCHAN / 8, 256>>>();
    scan_phase3<<<Bdim * NCHUNK, 256>>>(out);       // 1024 blocks
}